// round 17
// baseline (speedup 1.0000x reference)
#include <cuda_runtime.h>
#include <cuda_fp16.h>
#include <math.h>
#include <stdint.h>

#define BB 2
#define SS 2048
#define DIN 4096
#define NH 32
#define NKV 8
#define HD 64
#define QDIM 2048
#define KVDIM 512
#define QKVN 3072
#define DOUT 2048
#define MTOT 4096

// ---------------- scratch (__device__ globals) ------------------------------
__device__ __half g_hs[MTOT*DIN];
__device__ __half g_q[MTOT*QDIM];            // roped Q, pre-scaled by 0.125*log2(e)
__device__ __half g_k[MTOT*KVDIM];
__device__ __half g_v[MTOT*KVDIM];
__device__ __half g_ao[MTOT*QDIM];
__device__ __half g_wqkvT[QKVN*DIN];
__device__ __half g_woT[DOUT*QDIM];
__device__ float2 g_rope[SS*32];

// ---------------- helpers ----------------------------------------------------
__device__ __forceinline__ uint32_t smem_u32(const void* p) {
    uint32_t a;
    asm("{ .reg .u64 t; cvta.to.shared.u64 t, %1; cvt.u32.u64 %0, t; }" : "=r"(a) : "l"(p));
    return a;
}

#define LDSM4(r, addr)                                                           \
    asm volatile("ldmatrix.sync.aligned.m8n8.x4.shared.b16 {%0,%1,%2,%3}, [%4];" \
        : "=r"((r)[0]), "=r"((r)[1]), "=r"((r)[2]), "=r"((r)[3]) : "r"(addr))

#define LDSM4T(r, addr)                                                          \
    asm volatile("ldmatrix.sync.aligned.m8n8.x4.trans.shared.b16 {%0,%1,%2,%3}, [%4];" \
        : "=r"((r)[0]), "=r"((r)[1]), "=r"((r)[2]), "=r"((r)[3]) : "r"(addr))

#define MMA_F16(d, a, b0, b1)                                                    \
    asm volatile("mma.sync.aligned.m16n8k16.row.col.f32.f16.f16.f32 "            \
        "{%0,%1,%2,%3}, {%4,%5,%6,%7}, {%8,%9}, {%0,%1,%2,%3};"                  \
        : "+f"((d)[0]), "+f"((d)[1]), "+f"((d)[2]), "+f"((d)[3])                 \
        : "r"((a)[0]), "r"((a)[1]), "r"((a)[2]), "r"((a)[3]), "r"(b0), "r"(b1))

#define CP_ASYNC16(dst, src)                                                     \
    asm volatile("cp.async.cg.shared.global [%0], [%1], 16;" :: "r"(dst), "l"(src) : "memory")
#define CP_COMMIT()  asm volatile("cp.async.commit_group;" ::: "memory")
#define CP_WAIT1()   asm volatile("cp.async.wait_group 1;" ::: "memory")
#define CP_WAIT0()   asm volatile("cp.async.wait_group 0;" ::: "memory")

__device__ __forceinline__ uint32_t pack_f16(float lo, float hi) {
    uint32_t r;
    asm("cvt.rn.f16x2.f32 %0, %1, %2;" : "=r"(r) : "f"(hi), "f"(lo));
    return r;
}

// 2^x for x <= 0 (scores pre-scaled by log2(e); base change exact for softmax)
__device__ __forceinline__ float fast_exp2(float x) {
    float t = fmaxf(x, -126.0f);
    float fi = floorf(t);
    float f = t - fi;
    float p = 1.54035304e-4f;
    p = fmaf(p, f, 1.33335581e-3f);
    p = fmaf(p, f, 9.61812911e-3f);
    p = fmaf(p, f, 5.55041087e-2f);
    p = fmaf(p, f, 2.40226507e-1f);
    p = fmaf(p, f, 6.93147181e-1f);
    p = fmaf(p, f, 1.0f);
    return p * __uint_as_float(((uint32_t)((int)fi + 127)) << 23);
}

// ---------------- unified prep kernel (grid-sectioned) -------------------------
#define PREP_A 16384
#define PREP_B 12288
#define PREP_C 4096
#define PREP_D 256

__global__ void prep_all(const float* __restrict__ hs,
                         const float* __restrict__ Wq, const float* __restrict__ Wk,
                         const float* __restrict__ Wv, const float* __restrict__ Wo,
                         __half* __restrict__ hsh, __half* __restrict__ wqkvT,
                         __half* __restrict__ woT, float2* __restrict__ rope)
{
    __shared__ float t[32][33];
    int bid = blockIdx.x;
    int tid = threadIdx.x;

    if (bid < PREP_A) {
        int i = bid * 256 + tid;
        float4 v = ((const float4*)hs)[i];
        __half hh[4];
        hh[0] = __float2half_rn(v.x); hh[1] = __float2half_rn(v.y);
        hh[2] = __float2half_rn(v.z); hh[3] = __float2half_rn(v.w);
        ((uint2*)hsh)[i] = *(uint2*)hh;
        return;
    }
    if (bid >= PREP_A + PREP_B + PREP_C) {
        int idx = (bid - PREP_A - PREP_B - PREP_C) * 256 + tid;
        int p  = idx >> 5;
        int jp = idx & 31;
        float inv = exp2f(-(float)jp * (13.287712379549449f / 32.0f));
        float s, c;
        sincosf((float)p * inv, &s, &c);
        rope[idx] = make_float2(c, s);
        return;
    }

    int x = tid & 31, y = tid >> 5;
    if (bid < PREP_A + PREP_B) {
        int b2 = bid - PREP_A;
        int n0 = (b2 % (QKVN / 32)) * 32;
        int k0 = (b2 / (QKVN / 32)) * 32;
        const float* W; int srcN, sn0;
        if (n0 < QDIM)              { W = Wq; srcN = QDIM;  sn0 = n0; }
        else if (n0 < QDIM + KVDIM) { W = Wk; srcN = KVDIM; sn0 = n0 - QDIM; }
        else                        { W = Wv; srcN = KVDIM; sn0 = n0 - QDIM - KVDIM; }
        #pragma unroll
        for (int i = 0; i < 32; i += 8)
            t[y + i][x] = W[(size_t)(k0 + y + i) * srcN + sn0 + x];
        __syncthreads();
        #pragma unroll
        for (int i = 0; i < 32; i += 8)
            wqkvT[(size_t)(n0 + y + i) * DIN + k0 + x] = __float2half_rn(t[x][y + i]);
    } else {
        int b3 = bid - PREP_A - PREP_B;
        int n0 = (b3 % (DOUT / 32)) * 32;
        int k0 = (b3 / (DOUT / 32)) * 32;
        #pragma unroll
        for (int i = 0; i < 32; i += 8)
            t[y + i][x] = Wo[(size_t)(k0 + y + i) * DOUT + n0 + x];
        __syncthreads();
        #pragma unroll
        for (int i = 0; i < 32; i += 8)
            woT[(size_t)(n0 + y + i) * QDIM + k0 + x] = __float2half_rn(t[x][y + i]);
    }
}

// ---------------- 1-term fp16 HMMA GEMM core (K-chunk 64, 2-stage, 2 CTAs/SM) --
#define AST 72
#define TILE_E (128*AST)
#define STAGE_E (2*TILE_E)
#define GEMM_SMEM (2 * STAGE_E * 2)   // 73728 B -> 2 CTAs/SM

__device__ __forceinline__ void load_stage(
    uint32_t sbase_bytes, int tid, int bm, int bn, int k0, int K,
    const __half* __restrict__ A, const __half* __restrict__ B)
{
    #pragma unroll
    for (int i = 0; i < 8; i++) {
        int cid = tid + i * 256;
        int arr = cid >> 10;
        int rem = cid & 1023;
        int row = rem >> 3;
        int c16 = rem & 7;
        const __half* g = (arr == 0)
            ? A + (size_t)(bm + row) * K + k0 + c16 * 8
            : B + (size_t)(bn + row) * K + k0 + c16 * 8;
        uint32_t d = sbase_bytes + (uint32_t)(arr * TILE_E + row * AST + c16 * 8) * 2;
        CP_ASYNC16(d, g);
    }
    CP_COMMIT();
}

__device__ __forceinline__ void gemm_mainloop(
    float acc[2][8][4], uint32_t smb, int tid, int bm, int bn, int K,
    const __half* __restrict__ A, const __half* __restrict__ B)
{
    const int wid = tid >> 5;
    const int lane = tid & 31;
    const int wm = (wid & 3) * 32;
    const int wn = (wid >> 2) * 64;
    const int nch = K >> 6;

    load_stage(smb, tid, bm, bn, 0, K, A, B);

    for (int c = 0; c < nch; c++) {
        int buf = c & 1;
        CP_WAIT0();
        __syncthreads();

        if (c + 1 < nch)
            load_stage(smb + (uint32_t)(buf ^ 1) * STAGE_E * 2, tid, bm, bn,
                       (c + 1) << 6, K, A, B);

        uint32_t Ab = smb + (uint32_t)buf * STAGE_E * 2;
        uint32_t Bb = Ab + TILE_E * 2;

        #pragma unroll
        for (int ks = 0; ks < 4; ks++) {
            uint32_t ah[2][4], bf[4][4];
            #pragma unroll
            for (int mt = 0; mt < 2; mt++) {
                int row = wm + mt * 16 + (lane & 15);
                int col = ks * 16 + ((lane >> 4) << 3);
                LDSM4(ah[mt], Ab + (uint32_t)(row * AST + col) * 2);
            }
            #pragma unroll
            for (int p = 0; p < 4; p++) {
                int row = wn + p * 16 + (lane & 7) + ((lane >> 4) << 3);
                int col = ks * 16 + (((lane >> 3) & 1) << 3);
                LDSM4(bf[p], Bb + (uint32_t)(row * AST + col) * 2);
            }
            #pragma unroll
            for (int mt = 0; mt < 2; mt++) {
                #pragma unroll
                for (int nt = 0; nt < 8; nt++) {
                    uint32_t b0 = bf[nt >> 1][(nt & 1) * 2];
                    uint32_t b1 = bf[nt >> 1][(nt & 1) * 2 + 1];
                    MMA_F16(acc[mt][nt], ah[mt], b0, b1);
                }
            }
        }
    }
}

// O projection: fp32 C output (2 CTAs/SM)
__global__ __launch_bounds__(256, 2)
void hmma_gemm_c(const __half* __restrict__ A, const __half* __restrict__ B,
                 float* __restrict__ C, int M, int N, int K)
{
    extern __shared__ __half sm[];
    const int tid = threadIdx.x;
    const int wid = tid >> 5, lane = tid & 31;
    const int bm = blockIdx.y * 128, bn = blockIdx.x * 128;
    const int wm = (wid & 3) * 32, wn = (wid >> 2) * 64;

    float acc[2][8][4];
    #pragma unroll
    for (int mt = 0; mt < 2; mt++)
        #pragma unroll
        for (int nt = 0; nt < 8; nt++)
            #pragma unroll
            for (int j = 0; j < 4; j++) acc[mt][nt][j] = 0.f;

    gemm_mainloop(acc, smem_u32(sm), tid, bm, bn, K, A, B);

    #pragma unroll
    for (int mt = 0; mt < 2; mt++)
        #pragma unroll
        for (int nt = 0; nt < 8; nt++) {
            int r0  = bm + wm + mt * 16 + (lane >> 2);
            int col = bn + wn + nt * 8 + (lane & 3) * 2;
            *(float2*)&C[(size_t)r0 * N + col] = make_float2(acc[mt][nt][0], acc[mt][nt][1]);
            *(float2*)&C[(size_t)(r0 + 8) * N + col] = make_float2(acc[mt][nt][2], acc[mt][nt][3]);
        }
}

// QKV GEMM with fused RoPE epilogue (table-based; 2 CTAs/SM)
__global__ __launch_bounds__(256, 2)
void hmma_gemm_qkv(const __half* __restrict__ A, const __half* __restrict__ B,
                   const int* __restrict__ pos, const float2* __restrict__ rope,
                   __half* __restrict__ q, __half* __restrict__ k,
                   __half* __restrict__ v)
{
    extern __shared__ __half sm[];
    const int tid = threadIdx.x;
    const int wid = tid >> 5, lane = tid & 31;
    const int bm = blockIdx.y * 128, bn = blockIdx.x * 128;
    const int wm = (wid & 3) * 32, wn = (wid >> 2) * 64;

    float acc[2][8][4];
    #pragma unroll
    for (int mt = 0; mt < 2; mt++)
        #pragma unroll
        for (int nt = 0; nt < 8; nt++)
            #pragma unroll
            for (int j = 0; j < 4; j++) acc[mt][nt][j] = 0.f;

    gemm_mainloop(acc, smem_u32(sm), tid, bm, bn, DIN, A, B);

    const int ncol0 = bn + wn;
    if (ncol0 >= QDIM + KVDIM) {
        int colb = ncol0 - (QDIM + KVDIM) + (lane & 3) * 2;
        #pragma unroll
        for (int mt = 0; mt < 2; mt++)
            #pragma unroll
            for (int nt = 0; nt < 8; nt++)
                #pragma unroll
                for (int rs = 0; rs < 2; rs++) {
                    int m = bm + wm + mt * 16 + (lane >> 2) + rs * 8;
                    size_t o = (size_t)m * KVDIM + colb + nt * 8;
                    *(uint32_t*)&v[o] = pack_f16(acc[mt][nt][rs * 2], acc[mt][nt][rs * 2 + 1]);
                }
    } else {
        const int isQ = ncol0 < QDIM;
        const float scale = isQ ? 0.18033688011112042f : 1.0f;  // 0.125 * log2(e)
        __half* dst = isQ ? q : k;
        const int stride = isQ ? QDIM : KVDIM;
        const int colbase = isQ ? ncol0 : ncol0 - QDIM;
        #pragma unroll
        for (int mt = 0; mt < 2; mt++)
            #pragma unroll
            for (int rs = 0; rs < 2; rs++) {
                int m = bm + wm + mt * 16 + (lane >> 2) + rs * 8;
                const float2* rrow = rope + (size_t)pos[m] * 32;
                #pragma unroll
                for (int nt = 0; nt < 4; nt++) {
                    int jp0 = nt * 8 + (lane & 3) * 2;
                    float4 cs2 = *(const float4*)&rrow[jp0];
                    float y1[2], y2[2];
                    {
                        float v1 = acc[mt][nt][rs * 2], v2 = acc[mt][nt + 4][rs * 2];
                        y1[0] = (v1 * cs2.x - v2 * cs2.y) * scale;
                        y2[0] = (v2 * cs2.x + v1 * cs2.y) * scale;
                    }
                    {
                        float v1 = acc[mt][nt][rs * 2 + 1], v2 = acc[mt][nt + 4][rs * 2 + 1];
                        y1[1] = (v1 * cs2.z - v2 * cs2.w) * scale;
                        y2[1] = (v2 * cs2.z + v1 * cs2.w) * scale;
                    }
                    size_t o = (size_t)m * stride + colbase + jp0;
                    *(uint32_t*)&dst[o]      = pack_f16(y1[0], y1[1]);
                    *(uint32_t*)&dst[o + 32] = pack_f16(y2[0], y2[1]);
                }
            }
    }
}

// ---------------- HMMA flash attention (128-token KV chunks, 2 CTAs/SM) --------
#define QST 72
#define ATT_Q_E   (128*QST)
#define ATT_KV_E2 (128*QST)               // per array (K or V) per 128-token stage
#define ATT_KV_STAGE (2*ATT_KV_E2*2)      // K|V bytes = 36864
#define ATT_QBYTES (ATT_Q_E*2)
#define ATT_SMEM (ATT_QBYTES + 2*ATT_KV_STAGE)   // 92160 B -> 2 CTAs/SM

// load a 128-token K|V stage; token index clamped to tokmax (tail duplicates,
// values never consumed past the causal limit)
__device__ __forceinline__ void attn_load_kv2(
    uint32_t stage_base, int tid, int b, int kvh, int tok0, int tokmax,
    const __half* __restrict__ k, const __half* __restrict__ v)
{
    #pragma unroll
    for (int it = 0; it < 8; it++) {
        int cid = tid + it * 256;       // 0..2047
        int arr = cid >> 10;            // 0:K 1:V
        int rem = cid & 1023;
        int row = rem >> 3;             // 0..127
        int c   = rem & 7;
        int tok = tok0 + row;
        tok = (tok > tokmax) ? tokmax : tok;
        const __half* base = (arr == 0) ? k : v;
        const __half* src = base + (size_t)(b * SS + tok) * KVDIM + kvh * 64 + c * 8;
        CP_ASYNC16(stage_base + (uint32_t)arr * ATT_KV_E2 * 2 + (uint32_t)(row * QST + c * 8) * 2, src);
    }
    CP_COMMIT();
}

// process one 64-token sub-tile against the register-resident Q fragments
__device__ __forceinline__ void attn_tile(
    uint32_t K_o, uint32_t V_o, int diag, int lane, int rtile,
    const uint32_t qa_reg[4][4],
    float m_r[2], float l_r[2], float oacc[8][4])
{
    float sacc[8][4];
    #pragma unroll
    for (int nt = 0; nt < 8; nt++)
        #pragma unroll
        for (int j = 0; j < 4; j++) sacc[nt][j] = 0.f;

    #pragma unroll
    for (int ks = 0; ks < 4; ks++) {
        uint32_t kb[4][4];
        #pragma unroll
        for (int p = 0; p < 4; p++) {
            int row = p * 16 + (lane & 7) + ((lane >> 4) << 3);
            int col = ks * 16 + (((lane >> 3) & 1) << 3);
            LDSM4(kb[p], K_o + (uint32_t)(row * QST + col) * 2);
        }
        #pragma unroll
        for (int nt = 0; nt < 8; nt++) {
            uint32_t b0 = kb[nt >> 1][(nt & 1) * 2];
            uint32_t b1 = kb[nt >> 1][(nt & 1) * 2 + 1];
            MMA_F16(sacc[nt], qa_reg[ks], b0, b1);
        }
    }

    if (diag) {
        #pragma unroll
        for (int nt = 0; nt < 8; nt++)
            #pragma unroll
            for (int cc = 0; cc < 4; cc++) {
                int rloc = rtile + (lane >> 2) + ((cc >= 2) ? 8 : 0);
                int cloc = nt * 8 + (lane & 3) * 2 + (cc & 1);
                if (cloc > rloc) sacc[nt][cc] = -1e30f;
            }
    }

    {
        float mx0 = -1e30f, mx1 = -1e30f;
        #pragma unroll
        for (int nt = 0; nt < 8; nt++) {
            mx0 = fmaxf(mx0, fmaxf(sacc[nt][0], sacc[nt][1]));
            mx1 = fmaxf(mx1, fmaxf(sacc[nt][2], sacc[nt][3]));
        }
        mx0 = fmaxf(mx0, __shfl_xor_sync(0xffffffffu, mx0, 1));
        mx0 = fmaxf(mx0, __shfl_xor_sync(0xffffffffu, mx0, 2));
        mx1 = fmaxf(mx1, __shfl_xor_sync(0xffffffffu, mx1, 1));
        mx1 = fmaxf(mx1, __shfl_xor_sync(0xffffffffu, mx1, 2));
        float mn0 = fmaxf(m_r[0], mx0);
        float mn1 = fmaxf(m_r[1], mx1);
        float sc0 = fast_exp2(m_r[0] - mn0);
        float sc1 = fast_exp2(m_r[1] - mn1);
        m_r[0] = mn0; m_r[1] = mn1;
        float sum0 = 0.f, sum1 = 0.f;
        #pragma unroll
        for (int nt = 0; nt < 8; nt++) {
            float p0 = fast_exp2(sacc[nt][0] - mn0);
            float p1 = fast_exp2(sacc[nt][1] - mn0);
            float p2 = fast_exp2(sacc[nt][2] - mn1);
            float p3 = fast_exp2(sacc[nt][3] - mn1);
            sacc[nt][0] = p0; sacc[nt][1] = p1;
            sacc[nt][2] = p2; sacc[nt][3] = p3;
            sum0 += p0 + p1; sum1 += p2 + p3;
            oacc[nt][0] *= sc0; oacc[nt][1] *= sc0;
            oacc[nt][2] *= sc1; oacc[nt][3] *= sc1;
        }
        l_r[0] = l_r[0] * sc0 + sum0;
        l_r[1] = l_r[1] * sc1 + sum1;
    }

    #pragma unroll
    for (int j = 0; j < 4; j++) {
        uint32_t vb[4][4];
        int tok_off = (lane & 7) + (((lane >> 3) & 1) << 3);
        int d_off   = ((lane >> 4) & 1) << 3;
        #pragma unroll
        for (int p = 0; p < 4; p++) {
            uint32_t off = (uint32_t)((j * 16 + tok_off) * QST + p * 16 + d_off) * 2;
            LDSM4T(vb[p], V_o + off);
        }
        uint32_t ah[4];
        #pragma unroll
        for (int qd = 0; qd < 4; qd++) {
            int nt = 2 * j + (qd >> 1);
            ah[qd] = pack_f16(sacc[nt][(qd & 1) * 2], sacc[nt][(qd & 1) * 2 + 1]);
        }
        #pragma unroll
        for (int nt = 0; nt < 8; nt++) {
            uint32_t b0 = vb[nt >> 1][(nt & 1) * 2];
            uint32_t b1 = vb[nt >> 1][(nt & 1) * 2 + 1];
            MMA_F16(oacc[nt], ah, b0, b1);
        }
    }
}

__global__ __launch_bounds__(256, 2)
void attn_hmma(const __half* __restrict__ q, const __half* __restrict__ k,
               const __half* __restrict__ v, __half* __restrict__ ao)
{
    extern __shared__ __half smatt[];
    const int qt    = gridDim.x - 1 - blockIdx.x;
    const int hp    = blockIdx.y;
    const int kvh   = hp >> 1;
    const int hpair = hp & 1;
    const int b     = blockIdx.z;
    const int tid = threadIdx.x, wid = tid >> 5, lane = tid & 31;

    const uint32_t smb = smem_u32(smatt);
    const uint32_t Q_o = smb;

    #pragma unroll
    for (int it = 0; it < 4; it++) {
        int cid = tid + it * 256;
        int row = cid >> 3;
        int c   = cid & 7;
        const __half* src = q
            + (size_t)(b * SS + qt * 64 + (row & 63)) * QDIM
            + (kvh * 4 + hpair * 2 + (row >> 6)) * 64 + c * 8;
        CP_ASYNC16(Q_o + (uint32_t)(row * QST + c * 8) * 2, src);
    }
    CP_COMMIT();

    const int tokmax = qt * 64 + 63;
    attn_load_kv2(smb + ATT_QBYTES, tid, b, kvh, 0, tokmax, k, v);

    float m_r[2], l_r[2], oacc[8][4];
    m_r[0] = -1e30f; m_r[1] = -1e30f;
    l_r[0] = 0.f;    l_r[1] = 0.f;
    #pragma unroll
    for (int nt = 0; nt < 8; nt++)
        #pragma unroll
        for (int j = 0; j < 4; j++) oacc[nt][j] = 0.f;

    const int wrow  = wid * 16;
    const int hloc  = wid >> 2;
    const int rtile = (wid & 3) * 16;

    uint32_t qa_reg[4][4];

    const int nch = (qt + 2) >> 1;   // number of 128-token chunks
    for (int c = 0; c < nch; c++) {
        int buf = c & 1;
        CP_WAIT0();
        __syncthreads();

        if (c == 0) {
            #pragma unroll
            for (int ks = 0; ks < 4; ks++) {
                int row = wrow + (lane & 15);
                int col = ks * 16 + ((lane >> 4) << 3);
                LDSM4(qa_reg[ks], Q_o + (uint32_t)(row * QST + col) * 2);
            }
        }

        if (c + 1 < nch)
            attn_load_kv2(smb + ATT_QBYTES + (uint32_t)(buf ^ 1) * ATT_KV_STAGE,
                          tid, b, kvh, (c + 1) * 128, tokmax, k, v);

        const uint32_t stgK = smb + ATT_QBYTES + (uint32_t)buf * ATT_KV_STAGE;
        const uint32_t stgV = stgK + ATT_KV_E2 * 2;

        int kt0 = 2 * c;
        attn_tile(stgK, stgV, kt0 == qt, lane, rtile, qa_reg, m_r, l_r, oacc);
        if (kt0 + 1 <= qt)
            attn_tile(stgK + (uint32_t)(64 * QST) * 2, stgV + (uint32_t)(64 * QST) * 2,
                      kt0 + 1 == qt, lane, rtile, qa_reg, m_r, l_r, oacc);
    }

    l_r[0] += __shfl_xor_sync(0xffffffffu, l_r[0], 1);
    l_r[0] += __shfl_xor_sync(0xffffffffu, l_r[0], 2);
    l_r[1] += __shfl_xor_sync(0xffffffffu, l_r[1], 1);
    l_r[1] += __shfl_xor_sync(0xffffffffu, l_r[1], 2);
    float inv0 = 1.0f / l_r[0];
    float inv1 = 1.0f / l_r[1];
    int tok = qt * 64 + rtile + (lane >> 2);
    int colb = (kvh * 4 + hpair * 2 + hloc) * 64 + (lane & 3) * 2;
    #pragma unroll
    for (int nt = 0; nt < 8; nt++) {
        size_t o0 = (size_t)(b * SS + tok) * QDIM + colb + nt * 8;
        size_t o1 = o0 + (size_t)8 * QDIM;
        *(uint32_t*)&ao[o0] = pack_f16(oacc[nt][0] * inv0, oacc[nt][1] * inv0);
        *(uint32_t*)&ao[o1] = pack_f16(oacc[nt][2] * inv1, oacc[nt][3] * inv1);
    }
}

// ---------------------------------------------------------------------------
extern "C" void kernel_launch(void* const* d_in, const int* in_sizes, int n_in,
                              void* d_out, int out_size)
{
    (void)in_sizes; (void)n_in; (void)out_size;
    const float* hs  = (const float*)d_in[0];
    const int*   pos = (const int*)d_in[2];
    const float* Wq  = (const float*)d_in[3];
    const float* Wk  = (const float*)d_in[4];
    const float* Wv  = (const float*)d_in[5];
    const float* Wo  = (const float*)d_in[6];
    float* out = (float*)d_out;

    __half *hsb, *q, *k, *v, *ao, *w, *wo;
    float2* rope;
    cudaGetSymbolAddress((void**)&hsb, g_hs);
    cudaGetSymbolAddress((void**)&q,  g_q);
    cudaGetSymbolAddress((void**)&k,  g_k);
    cudaGetSymbolAddress((void**)&v,  g_v);
    cudaGetSymbolAddress((void**)&ao, g_ao);
    cudaGetSymbolAddress((void**)&w,  g_wqkvT);
    cudaGetSymbolAddress((void**)&wo, g_woT);
    cudaGetSymbolAddress((void**)&rope, g_rope);

    const int M = MTOT;
    cudaFuncSetAttribute(hmma_gemm_c,   cudaFuncAttributeMaxDynamicSharedMemorySize, GEMM_SMEM);
    cudaFuncSetAttribute(hmma_gemm_qkv, cudaFuncAttributeMaxDynamicSharedMemorySize, GEMM_SMEM);
    cudaFuncSetAttribute(attn_hmma,     cudaFuncAttributeMaxDynamicSharedMemorySize, ATT_SMEM);

    prep_all<<<PREP_A + PREP_B + PREP_C + PREP_D, 256>>>(hs, Wq, Wk, Wv, Wo, hsb, w, wo, rope); // 1
    hmma_gemm_qkv<<<dim3(QKVN / 128, M / 128), 256, GEMM_SMEM>>>(hsb, w, pos, rope, q, k, v);   // 2
    attn_hmma<<<dim3(SS / 64, 2 * NKV, BB), 256, ATT_SMEM>>>(q, k, v, ao);                      // 3
    hmma_gemm_c<<<dim3(DOUT / 128, M / 128), 256, GEMM_SMEM>>>(ao, wo, out, M, DOUT, QDIM);     // 4
}